// round 3
// baseline (speedup 1.0000x reference)
#include <cuda_runtime.h>

#define Bc 4
#define Lc 2048
#define Hc 8
#define Vc 64
#define HVc 512
#define TQ 32
#define TK 32
#define NTHREADS 256

// smem layout (floats):
// s_q:    [0,96)      query positions, 32 q * 3
// s_ils:  [96,104)    1/ls^2 per head
// s_kx:   [104,136)
// s_ky:   [136,168)
// s_kz:   [168,200)
// s_ms:   [200,232)   mask factor 0/1
// s_w:    [232,9448)  weights, stride 9 per (k,q) for bank-conflict-free access
// s_v:    [9448,25832) values tile 32k x 512 (float4-aligned: 9448%4==0)
#define OFF_Q   0
#define OFF_ILS 96
#define OFF_KX  104
#define OFF_KY  136
#define OFF_KZ  168
#define OFF_MS  200
#define OFF_W   232
#define OFF_V   9448
#define SMEM_FLOATS 25832

// normalized attended output [B, Lq, H*V], consumed by projection GEMM
__device__ float g_att[Bc * Lc * HVc];

__global__ __launch_bounds__(NTHREADS, 2)
void attend_kernel(const float* __restrict__ qpos,
                   const float* __restrict__ kpos,
                   const float* __restrict__ values,
                   const int*   __restrict__ mask,
                   const float* __restrict__ ls)
{
    extern __shared__ float sm[];
    float*  s_q   = sm + OFF_Q;
    float*  s_ils = sm + OFF_ILS;
    float*  s_kx  = sm + OFF_KX;
    float*  s_ky  = sm + OFF_KY;
    float*  s_kz  = sm + OFF_KZ;
    float*  s_ms  = sm + OFF_MS;
    float*  s_w   = sm + OFF_W;
    float4* s_v4  = (float4*)(sm + OFF_V);

    const int tid = threadIdx.x;
    const int b  = blockIdx.x >> 6;     // 64 q-tiles per batch
    const int qt = blockIdx.x & 63;

    // one-time loads
    if (tid < 96) s_q[tid] = qpos[(b * Lc + qt * TQ) * 3 + tid];
    if (tid < 8) { float l = ls[tid]; s_ils[tid] = 1.0f / (l * l); }

    // thread mapping for accumulate phase:
    //   vc = v-chunk (4 chunks of 16), h = head, qg = query group (4 q each)
    const int vc = tid & 3;
    const int h  = (tid >> 2) & 7;
    const int qg = tid >> 5;

    float acc[4][16];
    #pragma unroll
    for (int i = 0; i < 4; i++)
        #pragma unroll
        for (int j = 0; j < 16; j++) acc[i][j] = 0.0f;
    float den[4] = {1e-5f, 1e-5f, 1e-5f, 1e-5f};

    const float4* vals4 = (const float4*)values;

    for (int k0 = 0; k0 < Lc; k0 += TK) {
        __syncthreads();   // protect s_w / s_v from previous iteration's readers

        if (tid < TK) {
            const float* kp = kpos + (b * Lc + k0 + tid) * 3;
            s_kx[tid] = kp[0];
            s_ky[tid] = kp[1];
            s_kz[tid] = kp[2];
            s_ms[tid] = mask[b * Lc + k0 + tid] ? 0.0f : 1.0f;
        }
        // values tile: 32 keys * 512 floats contiguous -> coalesced float4
        {
            const int vbase = (b * Lc + k0) * (HVc / 4);
            #pragma unroll
            for (int i = 0; i < 16; i++)
                s_v4[tid + i * NTHREADS] = vals4[vbase + tid + i * NTHREADS];
        }
        __syncthreads();

        // ---- phase A: weights w[k][q][h] = mask * exp(-d2/ls^2) ----
        #pragma unroll
        for (int j = 0; j < 4; j++) {
            const int p = tid + j * NTHREADS;
            const int q = p & 31;     // consecutive across lanes -> conflict-free STS
            const int k = p >> 5;     // warp-uniform -> uniform mask branch
            const float dx = s_q[q * 3 + 0] - s_kx[k];
            const float dy = s_q[q * 3 + 1] - s_ky[k];
            const float dz = s_q[q * 3 + 2] - s_kz[k];
            const float d2 = dx * dx + dy * dy + dz * dz;
            float* wp = s_w + (k * TQ + q) * 9;
            if (s_ms[k] != 0.0f) {
                #pragma unroll
                for (int hh = 0; hh < 8; hh++)
                    wp[hh] = __expf(-d2 * s_ils[hh]);
            } else {
                #pragma unroll
                for (int hh = 0; hh < 8; hh++)
                    wp[hh] = 0.0f;
            }
        }
        __syncthreads();

        // ---- phase B: accumulate (4 q) x (head h) x (16 v) per thread ----
        #pragma unroll 4
        for (int k = 0; k < TK; k++) {
            float w0 = s_w[(k * TQ + qg * 4 + 0) * 9 + h];
            float w1 = s_w[(k * TQ + qg * 4 + 1) * 9 + h];
            float w2 = s_w[(k * TQ + qg * 4 + 2) * 9 + h];
            float w3 = s_w[(k * TQ + qg * 4 + 3) * 9 + h];
            den[0] += w0; den[1] += w1; den[2] += w2; den[3] += w3;

            const int vb = k * (HVc / 4) + h * 16 + vc * 4;
            float4 v0 = s_v4[vb + 0];
            float4 v1 = s_v4[vb + 1];
            float4 v2 = s_v4[vb + 2];
            float4 v3 = s_v4[vb + 3];

            #pragma unroll
            for (int i = 0; i < 4; i++) {
                const float w = (i == 0) ? w0 : (i == 1) ? w1 : (i == 2) ? w2 : w3;
                acc[i][0]  += w * v0.x;  acc[i][1]  += w * v0.y;
                acc[i][2]  += w * v0.z;  acc[i][3]  += w * v0.w;
                acc[i][4]  += w * v1.x;  acc[i][5]  += w * v1.y;
                acc[i][6]  += w * v1.z;  acc[i][7]  += w * v1.w;
                acc[i][8]  += w * v2.x;  acc[i][9]  += w * v2.y;
                acc[i][10] += w * v2.z;  acc[i][11] += w * v2.w;
                acc[i][12] += w * v3.x;  acc[i][13] += w * v3.y;
                acc[i][14] += w * v3.z;  acc[i][15] += w * v3.w;
            }
        }
    }

    // ---- epilogue: normalize and write attended ----
    float4* att4 = (float4*)g_att;
    #pragma unroll
    for (int i = 0; i < 4; i++) {
        const int q = qt * TQ + qg * 4 + i;
        const float inv = 1.0f / den[i];
        const int base = ((b * Lc + q) * HVc + h * Vc + vc * 16) >> 2;
        #pragma unroll
        for (int jj = 0; jj < 4; jj++) {
            att4[base + jj] = make_float4(acc[i][jj * 4 + 0] * inv,
                                          acc[i][jj * 4 + 1] * inv,
                                          acc[i][jj * 4 + 2] * inv,
                                          acc[i][jj * 4 + 3] * inv);
        }
    }
}

// ---- projection: out[8192,512] = g_att[8192,512] @ w_out[512,512]^T ----
#define BM 64
#define BN 64
#define BK 16

__global__ __launch_bounds__(256)
void proj_kernel(const float* __restrict__ W, float* __restrict__ out)
{
    __shared__ float As[BM][BK + 1];
    __shared__ float Ws[BN][BK + 1];

    const int tid = threadIdx.x;
    const int m0 = blockIdx.y * BM;
    const int n0 = blockIdx.x * BN;
    const int tx = tid & 15;       // n sub-tile
    const int ty = tid >> 4;       // m sub-tile

    const int lrow = tid >> 2;            // 0..63
    const int lk   = (tid & 3) * 4;       // 0,4,8,12

    float acc[4][4];
    #pragma unroll
    for (int i = 0; i < 4; i++)
        #pragma unroll
        for (int j = 0; j < 4; j++) acc[i][j] = 0.0f;

    for (int k0 = 0; k0 < HVc; k0 += BK) {
        float4 a = *(const float4*)&g_att[(m0 + lrow) * HVc + k0 + lk];
        float4 w = *(const float4*)&W[(n0 + lrow) * HVc + k0 + lk];
        As[lrow][lk + 0] = a.x; As[lrow][lk + 1] = a.y;
        As[lrow][lk + 2] = a.z; As[lrow][lk + 3] = a.w;
        Ws[lrow][lk + 0] = w.x; Ws[lrow][lk + 1] = w.y;
        Ws[lrow][lk + 2] = w.z; Ws[lrow][lk + 3] = w.w;
        __syncthreads();

        #pragma unroll
        for (int k = 0; k < BK; k++) {
            float av[4], bv[4];
            #pragma unroll
            for (int i = 0; i < 4; i++) av[i] = As[ty * 4 + i][k];
            #pragma unroll
            for (int j = 0; j < 4; j++) bv[j] = Ws[tx * 4 + j][k];
            #pragma unroll
            for (int i = 0; i < 4; i++)
                #pragma unroll
                for (int j = 0; j < 4; j++)
                    acc[i][j] += av[i] * bv[j];
        }
        __syncthreads();
    }

    #pragma unroll
    for (int i = 0; i < 4; i++) {
        float4 r = make_float4(acc[i][0], acc[i][1], acc[i][2], acc[i][3]);
        *(float4*)&out[(m0 + ty * 4 + i) * HVc + n0 + tx * 4] = r;
    }
}

extern "C" void kernel_launch(void* const* d_in, const int* in_sizes, int n_in,
                              void* d_out, int out_size)
{
    const float* qpos   = (const float*)d_in[0];
    const float* kpos   = (const float*)d_in[1];
    const float* values = (const float*)d_in[2];
    const int*   mask   = (const int*)  d_in[3];
    const float* ls     = (const float*)d_in[4];
    const float* w_out  = (const float*)d_in[5];
    float* out = (float*)d_out;

    const int smem_bytes = SMEM_FLOATS * (int)sizeof(float);
    cudaFuncSetAttribute(attend_kernel,
                         cudaFuncAttributeMaxDynamicSharedMemorySize, smem_bytes);

    attend_kernel<<<Bc * (Lc / TQ), NTHREADS, smem_bytes>>>(qpos, kpos, values, mask, ls);
    proj_kernel<<<dim3(HVc / BN, (Bc * Lc) / BM), 256>>>(w_out, out);
}

// round 4
// speedup vs baseline: 1.0003x; 1.0003x over previous
#include <cuda_runtime.h>

#define Bc 4
#define Lc 2048
#define Hc 8
#define Vc 64
#define HVc 512
#define TQ 32
#define TK 32
#define NTHREADS 256

// smem layout (floats):
// s_q:    [0,96)      query positions, 32 q * 3
// s_ils:  [96,104)    1/ls^2 per head
// s_kx:   [104,136)
// s_ky:   [136,168)
// s_kz:   [168,200)
// s_ms:   [200,232)   mask factor 0/1
// s_w:    [232,9448)  weights, stride 9 per (k,q) for bank-conflict-free access
// s_v:    [9448,25832) values tile 32k x 512 (float4-aligned: 9448%4==0)
#define OFF_Q   0
#define OFF_ILS 96
#define OFF_KX  104
#define OFF_KY  136
#define OFF_KZ  168
#define OFF_MS  200
#define OFF_W   232
#define OFF_V   9448
#define SMEM_FLOATS 25832

// normalized attended output [B, Lq, H*V], consumed by projection GEMM
__device__ float g_att[Bc * Lc * HVc];

__global__ __launch_bounds__(NTHREADS, 2)
void attend_kernel(const float* __restrict__ qpos,
                   const float* __restrict__ kpos,
                   const float* __restrict__ values,
                   const int*   __restrict__ mask,
                   const float* __restrict__ ls)
{
    extern __shared__ float sm[];
    float*  s_q   = sm + OFF_Q;
    float*  s_ils = sm + OFF_ILS;
    float*  s_kx  = sm + OFF_KX;
    float*  s_ky  = sm + OFF_KY;
    float*  s_kz  = sm + OFF_KZ;
    float*  s_ms  = sm + OFF_MS;
    float*  s_w   = sm + OFF_W;
    float4* s_v4  = (float4*)(sm + OFF_V);

    const int tid = threadIdx.x;
    const int b  = blockIdx.x >> 6;     // 64 q-tiles per batch
    const int qt = blockIdx.x & 63;

    // one-time loads
    if (tid < 96) s_q[tid] = qpos[(b * Lc + qt * TQ) * 3 + tid];
    if (tid < 8) { float l = ls[tid]; s_ils[tid] = 1.0f / (l * l); }

    // thread mapping for accumulate phase:
    //   vc = v-chunk (4 chunks of 16), h = head, qg = query group (4 q each)
    const int vc = tid & 3;
    const int h  = (tid >> 2) & 7;
    const int qg = tid >> 5;

    float acc[4][16];
    #pragma unroll
    for (int i = 0; i < 4; i++)
        #pragma unroll
        for (int j = 0; j < 16; j++) acc[i][j] = 0.0f;
    float den[4] = {1e-5f, 1e-5f, 1e-5f, 1e-5f};

    const float4* vals4 = (const float4*)values;

    for (int k0 = 0; k0 < Lc; k0 += TK) {
        __syncthreads();   // protect s_w / s_v from previous iteration's readers

        if (tid < TK) {
            const float* kp = kpos + (b * Lc + k0 + tid) * 3;
            s_kx[tid] = kp[0];
            s_ky[tid] = kp[1];
            s_kz[tid] = kp[2];
            s_ms[tid] = mask[b * Lc + k0 + tid] ? 0.0f : 1.0f;
        }
        // values tile: 32 keys * 512 floats contiguous -> coalesced float4
        {
            const int vbase = (b * Lc + k0) * (HVc / 4);
            #pragma unroll
            for (int i = 0; i < 16; i++)
                s_v4[tid + i * NTHREADS] = vals4[vbase + tid + i * NTHREADS];
        }
        __syncthreads();

        // ---- phase A: weights w[k][q][h] = mask * exp(-d2/ls^2) ----
        #pragma unroll
        for (int j = 0; j < 4; j++) {
            const int p = tid + j * NTHREADS;
            const int q = p & 31;     // consecutive across lanes -> conflict-free STS
            const int k = p >> 5;     // warp-uniform -> uniform mask branch
            const float dx = s_q[q * 3 + 0] - s_kx[k];
            const float dy = s_q[q * 3 + 1] - s_ky[k];
            const float dz = s_q[q * 3 + 2] - s_kz[k];
            const float d2 = dx * dx + dy * dy + dz * dz;
            float* wp = s_w + (k * TQ + q) * 9;
            if (s_ms[k] != 0.0f) {
                #pragma unroll
                for (int hh = 0; hh < 8; hh++)
                    wp[hh] = __expf(-d2 * s_ils[hh]);
            } else {
                #pragma unroll
                for (int hh = 0; hh < 8; hh++)
                    wp[hh] = 0.0f;
            }
        }
        __syncthreads();

        // ---- phase B: accumulate (4 q) x (head h) x (16 v) per thread ----
        #pragma unroll 4
        for (int k = 0; k < TK; k++) {
            float w0 = s_w[(k * TQ + qg * 4 + 0) * 9 + h];
            float w1 = s_w[(k * TQ + qg * 4 + 1) * 9 + h];
            float w2 = s_w[(k * TQ + qg * 4 + 2) * 9 + h];
            float w3 = s_w[(k * TQ + qg * 4 + 3) * 9 + h];
            den[0] += w0; den[1] += w1; den[2] += w2; den[3] += w3;

            const int vb = k * (HVc / 4) + h * 16 + vc * 4;
            float4 v0 = s_v4[vb + 0];
            float4 v1 = s_v4[vb + 1];
            float4 v2 = s_v4[vb + 2];
            float4 v3 = s_v4[vb + 3];

            #pragma unroll
            for (int i = 0; i < 4; i++) {
                const float w = (i == 0) ? w0 : (i == 1) ? w1 : (i == 2) ? w2 : w3;
                acc[i][0]  += w * v0.x;  acc[i][1]  += w * v0.y;
                acc[i][2]  += w * v0.z;  acc[i][3]  += w * v0.w;
                acc[i][4]  += w * v1.x;  acc[i][5]  += w * v1.y;
                acc[i][6]  += w * v1.z;  acc[i][7]  += w * v1.w;
                acc[i][8]  += w * v2.x;  acc[i][9]  += w * v2.y;
                acc[i][10] += w * v2.z;  acc[i][11] += w * v2.w;
                acc[i][12] += w * v3.x;  acc[i][13] += w * v3.y;
                acc[i][14] += w * v3.z;  acc[i][15] += w * v3.w;
            }
        }
    }

    // ---- epilogue: normalize and write attended ----
    float4* att4 = (float4*)g_att;
    #pragma unroll
    for (int i = 0; i < 4; i++) {
        const int q = qt * TQ + qg * 4 + i;
        const float inv = 1.0f / den[i];
        const int base = ((b * Lc + q) * HVc + h * Vc + vc * 16) >> 2;
        #pragma unroll
        for (int jj = 0; jj < 4; jj++) {
            att4[base + jj] = make_float4(acc[i][jj * 4 + 0] * inv,
                                          acc[i][jj * 4 + 1] * inv,
                                          acc[i][jj * 4 + 2] * inv,
                                          acc[i][jj * 4 + 3] * inv);
        }
    }
}

// ---- projection: out[8192,512] = g_att[8192,512] @ w_out[512,512]^T ----
#define BM 64
#define BN 64
#define BK 16

__global__ __launch_bounds__(256)
void proj_kernel(const float* __restrict__ W, float* __restrict__ out)
{
    __shared__ float As[BM][BK + 1];
    __shared__ float Ws[BN][BK + 1];

    const int tid = threadIdx.x;
    const int m0 = blockIdx.y * BM;
    const int n0 = blockIdx.x * BN;
    const int tx = tid & 15;       // n sub-tile
    const int ty = tid >> 4;       // m sub-tile

    const int lrow = tid >> 2;            // 0..63
    const int lk   = (tid & 3) * 4;       // 0,4,8,12

    float acc[4][4];
    #pragma unroll
    for (int i = 0; i < 4; i++)
        #pragma unroll
        for (int j = 0; j < 4; j++) acc[i][j] = 0.0f;

    for (int k0 = 0; k0 < HVc; k0 += BK) {
        float4 a = *(const float4*)&g_att[(m0 + lrow) * HVc + k0 + lk];
        float4 w = *(const float4*)&W[(n0 + lrow) * HVc + k0 + lk];
        As[lrow][lk + 0] = a.x; As[lrow][lk + 1] = a.y;
        As[lrow][lk + 2] = a.z; As[lrow][lk + 3] = a.w;
        Ws[lrow][lk + 0] = w.x; Ws[lrow][lk + 1] = w.y;
        Ws[lrow][lk + 2] = w.z; Ws[lrow][lk + 3] = w.w;
        __syncthreads();

        #pragma unroll
        for (int k = 0; k < BK; k++) {
            float av[4], bv[4];
            #pragma unroll
            for (int i = 0; i < 4; i++) av[i] = As[ty * 4 + i][k];
            #pragma unroll
            for (int j = 0; j < 4; j++) bv[j] = Ws[tx * 4 + j][k];
            #pragma unroll
            for (int i = 0; i < 4; i++)
                #pragma unroll
                for (int j = 0; j < 4; j++)
                    acc[i][j] += av[i] * bv[j];
        }
        __syncthreads();
    }

    #pragma unroll
    for (int i = 0; i < 4; i++) {
        float4 r = make_float4(acc[i][0], acc[i][1], acc[i][2], acc[i][3]);
        *(float4*)&out[(m0 + ty * 4 + i) * HVc + n0 + tx * 4] = r;
    }
}

extern "C" void kernel_launch(void* const* d_in, const int* in_sizes, int n_in,
                              void* d_out, int out_size)
{
    const float* qpos   = (const float*)d_in[0];
    const float* kpos   = (const float*)d_in[1];
    const float* values = (const float*)d_in[2];
    const int*   mask   = (const int*)  d_in[3];
    const float* ls     = (const float*)d_in[4];
    const float* w_out  = (const float*)d_in[5];
    float* out = (float*)d_out;

    const int smem_bytes = SMEM_FLOATS * (int)sizeof(float);
    cudaFuncSetAttribute(attend_kernel,
                         cudaFuncAttributeMaxDynamicSharedMemorySize, smem_bytes);

    attend_kernel<<<Bc * (Lc / TQ), NTHREADS, smem_bytes>>>(qpos, kpos, values, mask, ls);
    proj_kernel<<<dim3(HVc / BN, (Bc * Lc) / BM), 256>>>(w_out, out);
}

// round 5
// speedup vs baseline: 1.8891x; 1.8885x over previous
#include <cuda_runtime.h>

#define Bc 4
#define Lc 2048
#define Hc 8
#define Vc 64
#define HVc 512
#define TQ 32
#define TK 32
#define NTHREADS 256

typedef unsigned long long ull;

__device__ __forceinline__ void fma2(ull &c, ull a, ull b) {
    asm("fma.rn.f32x2 %0, %1, %2, %0;" : "+l"(c) : "l"(a), "l"(b));
}
__device__ __forceinline__ ull pack2(float lo, float hi) {
    ull r; asm("mov.b64 %0, {%1, %2};" : "=l"(r) : "f"(lo), "f"(hi)); return r;
}
__device__ __forceinline__ ull mul2(ull a, ull b) {
    ull r; asm("mul.rn.f32x2 %0, %1, %2;" : "=l"(r) : "l"(a), "l"(b)); return r;
}
__device__ __forceinline__ void unpack2(ull v, float &lo, float &hi) {
    asm("mov.b64 {%0, %1}, %2;" : "=f"(lo), "=f"(hi) : "l"(v));
}

// smem layout (floats):
// s_q:    [0,96)     query positions (also reused as s_den in epilogue)
// s_ils:  [96,104)
// s_kx/ky/kz/ms: [104,232)
// s_w:    [232,9448)  weights [k][h][q], row stride 36 floats (144B, 16B-aligned)
// s_v:    [9448,25832) values tile 32k x 512
#define OFF_Q   0
#define OFF_ILS 96
#define OFF_KX  104
#define OFF_KY  136
#define OFF_KZ  168
#define OFF_MS  200
#define OFF_W   232
#define OFF_V   9448
#define SMEM_FLOATS 25832
#define WSTRIDE 36

// normalized attended output [B, Lq, H*V], consumed by projection GEMM
__device__ float g_att[Bc * Lc * HVc];

__global__ __launch_bounds__(NTHREADS, 2)
void attend_kernel(const float* __restrict__ qpos,
                   const float* __restrict__ kpos,
                   const float* __restrict__ values,
                   const int*   __restrict__ mask,
                   const float* __restrict__ ls)
{
    extern __shared__ float sm[];
    float*  s_q   = sm + OFF_Q;
    float*  s_ils = sm + OFF_ILS;
    float*  s_kx  = sm + OFF_KX;
    float*  s_ky  = sm + OFF_KY;
    float*  s_kz  = sm + OFF_KZ;
    float*  s_ms  = sm + OFF_MS;
    float*  s_w   = sm + OFF_W;
    float*  s_v   = sm + OFF_V;
    float4* s_v4  = (float4*)s_v;

    const int tid  = threadIdx.x;
    const int lane = tid & 31;
    const int warp = tid >> 5;
    const int b  = blockIdx.x >> 6;
    const int qt = blockIdx.x & 63;

    if (tid < 96) s_q[tid] = qpos[(b * Lc + qt * TQ) * 3 + tid];
    if (tid < 8) { float l = ls[tid]; s_ils[tid] = 1.0f / (l * l); }
    __syncthreads();

    // hoisted per-thread constants
    const float qx = s_q[lane * 3 + 0];
    const float qy = s_q[lane * 3 + 1];
    const float qz = s_q[lane * 3 + 2];
    float rils[8];
    #pragma unroll
    for (int hh = 0; hh < 8; hh++) rils[hh] = s_ils[hh];

    // accumulator: warp = head h; lane covers v-elements {lane, lane+32};
    // q packed in pairs: accA/accB[qp] = (q=2qp, q=2qp+1) for v0/v1
    ull accA[16], accB[16];
    #pragma unroll
    for (int i = 0; i < 16; i++) { accA[i] = 0ULL; accB[i] = 0ULL; }
    float denr = 0.0f;   // held by the (q=lane, h=warp) mapping

    const float4* vals4 = (const float4*)values;

    for (int k0 = 0; k0 < Lc; k0 += TK) {
        __syncthreads();   // previous tile's readers done

        if (tid < TK) {
            const float* kp = kpos + (b * Lc + k0 + tid) * 3;
            s_kx[tid] = kp[0];
            s_ky[tid] = kp[1];
            s_kz[tid] = kp[2];
            s_ms[tid] = mask[b * Lc + k0 + tid] ? 0.0f : 1.0f;
        }
        {
            const int vbase = (b * Lc + k0) * (HVc / 4);
            #pragma unroll
            for (int i = 0; i < 16; i++)
                s_v4[tid + i * NTHREADS] = vals4[vbase + tid + i * NTHREADS];
        }
        __syncthreads();

        // ---- phase A: w[k][h][q] = mask * exp(-d2 / ls^2) ----
        #pragma unroll
        for (int j = 0; j < 4; j++) {
            const int k = warp + j * 8;           // warp-uniform
            const float dx = qx - s_kx[k];
            const float dy = qy - s_ky[k];
            const float dz = qz - s_kz[k];
            const float d2 = dx * dx + dy * dy + dz * dz;
            float* wp = s_w + (k * 8) * WSTRIDE + lane;
            if (s_ms[k] != 0.0f) {
                #pragma unroll
                for (int hh = 0; hh < 8; hh++)
                    wp[hh * WSTRIDE] = __expf(-d2 * rils[hh]);
            } else {
                #pragma unroll
                for (int hh = 0; hh < 8; hh++)
                    wp[hh * WSTRIDE] = 0.0f;
            }
        }
        __syncthreads();

        // ---- den partial: thread (q=lane, h=warp) sums this tile's k ----
        {
            float dsum = 0.0f;
            #pragma unroll 8
            for (int k = 0; k < TK; k++)
                dsum += s_w[(k * 8 + warp) * WSTRIDE + lane];
            denr += dsum;
        }

        // ---- phase B: packed f32x2 accumulation ----
        {
            const float* vb_base = s_v + warp * 64 + lane;
            #pragma unroll 4
            for (int k = 0; k < TK; k++) {
                const float va = vb_base[k * HVc];
                const float vbx = vb_base[k * HVc + 32];
                const ull va2 = pack2(va, va);
                const ull vb2 = pack2(vbx, vbx);
                const ulonglong2* w2 =
                    (const ulonglong2*)(s_w + (k * 8 + warp) * WSTRIDE);
                #pragma unroll
                for (int j = 0; j < 8; j++) {
                    const ulonglong2 ww = w2[j];
                    fma2(accA[2 * j],     ww.x, va2);
                    fma2(accB[2 * j],     ww.x, vb2);
                    fma2(accA[2 * j + 1], ww.y, va2);
                    fma2(accB[2 * j + 1], ww.y, vb2);
                }
            }
        }
    }

    // ---- epilogue: normalize + write ----
    __syncthreads();                       // all phase-B reads of s_w done
    float* s_den = sm;                     // reuse s_q area: [h][q] = 8 x 32
    s_den[warp * 32 + lane] = 1.0f / (denr + 1e-5f);
    __syncthreads();

    #pragma unroll
    for (int qp = 0; qp < 16; qp++) {
        const ull inv = *(const ull*)(s_den + warp * 32 + 2 * qp);
        const ull ra = mul2(accA[qp], inv);
        const ull rb = mul2(accB[qp], inv);
        float a0, a1, b0, b1;
        unpack2(ra, a0, a1);
        unpack2(rb, b0, b1);
        const int q = qt * TQ + 2 * qp;
        const size_t base = (size_t)(b * Lc + q) * HVc + warp * 64 + lane;
        g_att[base]            = a0;
        g_att[base + 32]       = b0;
        g_att[base + HVc]      = a1;
        g_att[base + HVc + 32] = b1;
    }
}

// ---- projection: out[8192,512] = g_att[8192,512] @ w_out[512,512]^T ----
#define PBM 64
#define PBN 128
#define PBK 16
#define WPAD 132

__global__ __launch_bounds__(256)
void proj_kernel(const float* __restrict__ W, float* __restrict__ out)
{
    __shared__ float As[PBM][PBK + 1];   // [m][k]
    __shared__ float Ws[PBK][WPAD];      // [k][n], n contiguous for packed pairs

    const int tid = threadIdx.x;
    const int m0 = blockIdx.y * PBM;
    const int n0 = blockIdx.x * PBN;
    const int tx = tid & 15;      // n sub-tile: 8 n each
    const int ty = tid >> 4;      // m sub-tile: 4 m each

    ull acc[4][4];
    #pragma unroll
    for (int i = 0; i < 4; i++)
        #pragma unroll
        for (int j = 0; j < 4; j++) acc[i][j] = 0ULL;

    const int arow = tid >> 2, ak = (tid & 3) * 4;
    const int wn = tid >> 1, wk = (tid & 1) * 8;

    for (int k0 = 0; k0 < HVc; k0 += PBK) {
        {
            float4 a = *(const float4*)&g_att[(size_t)(m0 + arow) * HVc + k0 + ak];
            As[arow][ak + 0] = a.x; As[arow][ak + 1] = a.y;
            As[arow][ak + 2] = a.z; As[arow][ak + 3] = a.w;

            float4 w0 = *(const float4*)&W[(size_t)(n0 + wn) * HVc + k0 + wk];
            float4 w1 = *(const float4*)&W[(size_t)(n0 + wn) * HVc + k0 + wk + 4];
            Ws[wk + 0][wn] = w0.x; Ws[wk + 1][wn] = w0.y;
            Ws[wk + 2][wn] = w0.z; Ws[wk + 3][wn] = w0.w;
            Ws[wk + 4][wn] = w1.x; Ws[wk + 5][wn] = w1.y;
            Ws[wk + 6][wn] = w1.z; Ws[wk + 7][wn] = w1.w;
        }
        __syncthreads();

        #pragma unroll
        for (int k = 0; k < PBK; k++) {
            ull ap[4];
            #pragma unroll
            for (int i = 0; i < 4; i++) {
                const float a = As[ty * 4 + i][k];
                ap[i] = pack2(a, a);
            }
            const ulonglong2 wA = *(const ulonglong2*)&Ws[k][tx * 8];
            const ulonglong2 wB = *(const ulonglong2*)&Ws[k][tx * 8 + 4];
            #pragma unroll
            for (int i = 0; i < 4; i++) {
                fma2(acc[i][0], ap[i], wA.x);
                fma2(acc[i][1], ap[i], wA.y);
                fma2(acc[i][2], ap[i], wB.x);
                fma2(acc[i][3], ap[i], wB.y);
            }
        }
        __syncthreads();
    }

    #pragma unroll
    for (int i = 0; i < 4; i++) {
        float r0, r1, r2, r3, r4, r5, r6, r7;
        unpack2(acc[i][0], r0, r1);
        unpack2(acc[i][1], r2, r3);
        unpack2(acc[i][2], r4, r5);
        unpack2(acc[i][3], r6, r7);
        const size_t ro = (size_t)(m0 + ty * 4 + i) * HVc + n0 + tx * 8;
        *(float4*)&out[ro]     = make_float4(r0, r1, r2, r3);
        *(float4*)&out[ro + 4] = make_float4(r4, r5, r6, r7);
    }
}

extern "C" void kernel_launch(void* const* d_in, const int* in_sizes, int n_in,
                              void* d_out, int out_size)
{
    const float* qpos   = (const float*)d_in[0];
    const float* kpos   = (const float*)d_in[1];
    const float* values = (const float*)d_in[2];
    const int*   mask   = (const int*)  d_in[3];
    const float* ls     = (const float*)d_in[4];
    const float* w_out  = (const float*)d_in[5];
    float* out = (float*)d_out;

    const int smem_bytes = SMEM_FLOATS * (int)sizeof(float);
    cudaFuncSetAttribute(attend_kernel,
                         cudaFuncAttributeMaxDynamicSharedMemorySize, smem_bytes);

    attend_kernel<<<Bc * (Lc / TQ), NTHREADS, smem_bytes>>>(qpos, kpos, values, mask, ls);
    proj_kernel<<<dim3(HVc / PBN, (Bc * Lc) / PBM), 256>>>(w_out, out);
}

// round 6
// speedup vs baseline: 3.5508x; 1.8797x over previous
#include <cuda_runtime.h>

#define Bc 4
#define Lc 2048
#define Hc 8
#define Vc 64
#define HVc 512
#define TQ 32
#define TK 32
#define NTHREADS 256

typedef unsigned long long ull;

__device__ __forceinline__ void fma2(ull &c, ull a, ull b) {
    asm("fma.rn.f32x2 %0, %1, %2, %0;" : "+l"(c) : "l"(a), "l"(b));
}
__device__ __forceinline__ ull pack2(float lo, float hi) {
    ull r; asm("mov.b64 %0, {%1, %2};" : "=l"(r) : "f"(lo), "f"(hi)); return r;
}
__device__ __forceinline__ ull mul2(ull a, ull b) {
    ull r; asm("mul.rn.f32x2 %0, %1, %2;" : "=l"(r) : "l"(a), "l"(b)); return r;
}
__device__ __forceinline__ void unpack2(ull v, float &lo, float &hi) {
    asm("mov.b64 {%0, %1}, %2;" : "=f"(lo), "=f"(hi) : "l"(v));
}

// ---- persistent device scratch (no allocations allowed) ----
__device__ float g_att[Bc * Lc * HVc];      // normalized attended [B, Lq, H*V]
__device__ float g_vals_c[Bc * Lc * HVc];   // compacted values
__device__ float g_kpos_c[Bc * Lc * 3];     // compacted key positions (pad = 1000)
__device__ int   g_idx[Bc * Lc];
__device__ int   g_cnt[Bc];

// ================= compaction: unmasked key indices per batch =================
__global__ void compact_kernel(const int* __restrict__ mask)
{
    const int b = blockIdx.x;
    const int lane = threadIdx.x;
    int cnt = 0;
    for (int k0 = 0; k0 < Lc; k0 += 32) {
        const int k = k0 + lane;
        const bool u = (mask[b * Lc + k] == 0);
        const unsigned bal = __ballot_sync(0xFFFFFFFFu, u);
        if (u) {
            const int pos = cnt + __popc(bal & ((1u << lane) - 1u));
            g_idx[b * Lc + pos] = k;
        }
        cnt += __popc(bal);
    }
    if (lane == 0) g_cnt[b] = cnt;
}

// ============ gather: values + kpos of unmasked keys, pad to mult of 32 ============
__global__ void gather_kernel(const float* __restrict__ kpos,
                              const float* __restrict__ values)
{
    const int b  = blockIdx.x >> 5;
    const int j0 = (blockIdx.x & 31) * 64;
    const int tid = threadIdx.x;
    __shared__ int s_idx[64];
    __shared__ int s_n[2];

    if (tid == 0) { int c = g_cnt[b]; s_n[0] = c; s_n[1] = (c + 31) & ~31; }
    if (tid < 64 && j0 + tid < Lc) s_idx[tid] = g_idx[b * Lc + j0 + tid];
    __syncthreads();
    const int cnt = s_n[0];
    const int pad = s_n[1];
    const int jend = min(j0 + 64, pad);
    if (jend <= j0) return;
    const int nrows = jend - j0;

    const float4* v4 = (const float4*)values;
    float4* g4 = (float4*)g_vals_c;
    for (int e = tid; e < nrows * 128; e += NTHREADS) {
        const int jl = e >> 7;
        const int c  = e & 127;
        const int j  = j0 + jl;
        float4 v;
        if (j < cnt) v = v4[(size_t)(b * Lc + s_idx[jl]) * 128 + c];
        else         v = make_float4(0.f, 0.f, 0.f, 0.f);
        g4[(size_t)(b * Lc + j) * 128 + c] = v;
    }
    for (int e = tid; e < nrows * 3; e += NTHREADS) {
        const int jl = e / 3;
        const int d  = e % 3;
        const int j  = j0 + jl;
        float p = (j < cnt) ? kpos[(size_t)(b * Lc + s_idx[jl]) * 3 + d] : 1000.0f;
        g_kpos_c[(size_t)(b * Lc + j) * 3 + d] = p;
    }
}

// =========================== attend over compacted keys ===========================
// smem layout (floats):
// s_q:[0,96)  s_ils:[96,104)  s_kx:[104,136) s_ky:[136,168) s_kz:[168,200)
// s_w:[232,9448) weights [k][h][q] stride 36 | s_v:[9448,25832)
#define OFF_Q   0
#define OFF_ILS 96
#define OFF_KX  104
#define OFF_KY  136
#define OFF_KZ  168
#define OFF_W   232
#define OFF_V   9448
#define SMEM_FLOATS 25832
#define WSTRIDE 36

__global__ __launch_bounds__(NTHREADS, 2)
void attend_kernel(const float* __restrict__ qpos,
                   const float* __restrict__ ls)
{
    extern __shared__ float sm[];
    float*  s_q   = sm + OFF_Q;
    float*  s_ils = sm + OFF_ILS;
    float*  s_kx  = sm + OFF_KX;
    float*  s_ky  = sm + OFF_KY;
    float*  s_kz  = sm + OFF_KZ;
    float*  s_w   = sm + OFF_W;
    float*  s_v   = sm + OFF_V;
    float4* s_v4  = (float4*)s_v;

    const int tid  = threadIdx.x;
    const int lane = tid & 31;
    const int warp = tid >> 5;
    const int b  = blockIdx.x >> 6;
    const int qt = blockIdx.x & 63;

    if (tid < 96) s_q[tid] = qpos[(b * Lc + qt * TQ) * 3 + tid];
    if (tid < 8) { float l = ls[tid]; s_ils[tid] = 1.0f / (l * l); }
    __syncthreads();

    const float qx = s_q[lane * 3 + 0];
    const float qy = s_q[lane * 3 + 1];
    const float qz = s_q[lane * 3 + 2];
    float rils[8];
    #pragma unroll
    for (int hh = 0; hh < 8; hh++) rils[hh] = s_ils[hh];

    const int nk_pad = (g_cnt[b] + 31) & ~31;

    // warp = head; lane covers v-elements {lane, lane+32}; q in 16 pairs
    ull accA[16], accB[16];
    #pragma unroll
    for (int i = 0; i < 16; i++) { accA[i] = 0ULL; accB[i] = 0ULL; }
    float denr = 0.0f;

    const float4* vals4 = (const float4*)g_vals_c;

    for (int k0 = 0; k0 < nk_pad; k0 += TK) {
        __syncthreads();

        if (tid < TK) {
            const float* kp = g_kpos_c + (size_t)(b * Lc + k0 + tid) * 3;
            s_kx[tid] = kp[0];
            s_ky[tid] = kp[1];
            s_kz[tid] = kp[2];
        }
        {
            const size_t vbase = (size_t)(b * Lc + k0) * (HVc / 4);
            #pragma unroll
            for (int i = 0; i < 16; i++)
                s_v4[tid + i * NTHREADS] = vals4[vbase + tid + i * NTHREADS];
        }
        __syncthreads();

        // phase A: w[k][h][q] = exp(-d2/ls^2)  (pad rows underflow to 0)
        #pragma unroll
        for (int j = 0; j < 4; j++) {
            const int k = warp + j * 8;
            const float dx = qx - s_kx[k];
            const float dy = qy - s_ky[k];
            const float dz = qz - s_kz[k];
            const float d2 = dx * dx + dy * dy + dz * dz;
            float* wp = s_w + (k * 8) * WSTRIDE + lane;
            #pragma unroll
            for (int hh = 0; hh < 8; hh++)
                wp[hh * WSTRIDE] = __expf(-d2 * rils[hh]);
        }
        __syncthreads();

        // den partial: thread (q=lane, h=warp)
        {
            float dsum = 0.0f;
            #pragma unroll 8
            for (int k = 0; k < TK; k++)
                dsum += s_w[(k * 8 + warp) * WSTRIDE + lane];
            denr += dsum;
        }

        // phase B: packed f32x2 accumulation
        {
            const float* vb_base = s_v + warp * 64 + lane;
            #pragma unroll 4
            for (int k = 0; k < TK; k++) {
                const float va  = vb_base[k * HVc];
                const float vbx = vb_base[k * HVc + 32];
                const ull va2 = pack2(va, va);
                const ull vb2 = pack2(vbx, vbx);
                const ulonglong2* w2 =
                    (const ulonglong2*)(s_w + (k * 8 + warp) * WSTRIDE);
                #pragma unroll
                for (int j = 0; j < 8; j++) {
                    const ulonglong2 ww = w2[j];
                    fma2(accA[2 * j],     ww.x, va2);
                    fma2(accB[2 * j],     ww.x, vb2);
                    fma2(accA[2 * j + 1], ww.y, va2);
                    fma2(accB[2 * j + 1], ww.y, vb2);
                }
            }
        }
    }

    // epilogue: normalize + write
    __syncthreads();
    float* s_den = sm;          // reuse s_q area: [h][q]
    s_den[warp * 32 + lane] = 1.0f / (denr + 1e-5f);
    __syncthreads();

    #pragma unroll
    for (int qp = 0; qp < 16; qp++) {
        const ull inv = *(const ull*)(s_den + warp * 32 + 2 * qp);
        const ull ra = mul2(accA[qp], inv);
        const ull rb = mul2(accB[qp], inv);
        float a0, a1, b0, b1;
        unpack2(ra, a0, a1);
        unpack2(rb, b0, b1);
        const int q = qt * TQ + 2 * qp;
        const size_t base = (size_t)(b * Lc + q) * HVc + warp * 64 + lane;
        g_att[base]            = a0;
        g_att[base + 32]       = b0;
        g_att[base + HVc]      = a1;
        g_att[base + HVc + 32] = b1;
    }
}

// ====== projection: out[8192,512] = g_att @ W^T, 128x128 tile, f32x2 ======
#define PM 128
#define PN 128
#define PK 16

__global__ __launch_bounds__(256, 2)
void proj_kernel(const float* __restrict__ W, float* __restrict__ out)
{
    __shared__ __align__(16) float As[PK][PM + 4];   // [k][m], stride 132
    __shared__ __align__(16) float Ws[PK][PN + 2];   // [k][n], stride 130

    const int tid = threadIdx.x;
    const int m0 = blockIdx.y * PM;
    const int n0 = blockIdx.x * PN;
    const int tx = tid & 15;      // n-pairs {tx, tx+16, tx+32, tx+48}
    const int ty = tid >> 4;      // m rows ty*8 .. ty*8+7

    const int lrow = tid >> 1;        // 0..127
    const int lk   = (tid & 1) * 8;   // 0 or 8

    ull acc[8][4];
    #pragma unroll
    for (int i = 0; i < 8; i++)
        #pragma unroll
        for (int j = 0; j < 4; j++) acc[i][j] = 0ULL;

    // prefetch stage 0
    float4 ra0 = *(const float4*)&g_att[(size_t)(m0 + lrow) * HVc + lk];
    float4 ra1 = *(const float4*)&g_att[(size_t)(m0 + lrow) * HVc + lk + 4];
    float4 rw0 = *(const float4*)&W[(size_t)(n0 + lrow) * HVc + lk];
    float4 rw1 = *(const float4*)&W[(size_t)(n0 + lrow) * HVc + lk + 4];

    for (int k0 = 0; k0 < HVc; k0 += PK) {
        As[lk + 0][lrow] = ra0.x; As[lk + 1][lrow] = ra0.y;
        As[lk + 2][lrow] = ra0.z; As[lk + 3][lrow] = ra0.w;
        As[lk + 4][lrow] = ra1.x; As[lk + 5][lrow] = ra1.y;
        As[lk + 6][lrow] = ra1.z; As[lk + 7][lrow] = ra1.w;
        Ws[lk + 0][lrow] = rw0.x; Ws[lk + 1][lrow] = rw0.y;
        Ws[lk + 2][lrow] = rw0.z; Ws[lk + 3][lrow] = rw0.w;
        Ws[lk + 4][lrow] = rw1.x; Ws[lk + 5][lrow] = rw1.y;
        Ws[lk + 6][lrow] = rw1.z; Ws[lk + 7][lrow] = rw1.w;
        __syncthreads();

        if (k0 + PK < HVc) {
            const int kn = k0 + PK;
            ra0 = *(const float4*)&g_att[(size_t)(m0 + lrow) * HVc + kn + lk];
            ra1 = *(const float4*)&g_att[(size_t)(m0 + lrow) * HVc + kn + lk + 4];
            rw0 = *(const float4*)&W[(size_t)(n0 + lrow) * HVc + kn + lk];
            rw1 = *(const float4*)&W[(size_t)(n0 + lrow) * HVc + kn + lk + 4];
        }

        #pragma unroll
        for (int k = 0; k < PK; k++) {
            float4 a0 = *(const float4*)&As[k][ty * 8];
            float4 a1 = *(const float4*)&As[k][ty * 8 + 4];
            ull ap[8];
            ap[0] = pack2(a0.x, a0.x); ap[1] = pack2(a0.y, a0.y);
            ap[2] = pack2(a0.z, a0.z); ap[3] = pack2(a0.w, a0.w);
            ap[4] = pack2(a1.x, a1.x); ap[5] = pack2(a1.y, a1.y);
            ap[6] = pack2(a1.z, a1.z); ap[7] = pack2(a1.w, a1.w);
            const ull w0 = *(const ull*)&Ws[k][2 * tx];
            const ull w1 = *(const ull*)&Ws[k][2 * tx + 32];
            const ull w2 = *(const ull*)&Ws[k][2 * tx + 64];
            const ull w3 = *(const ull*)&Ws[k][2 * tx + 96];
            #pragma unroll
            for (int i = 0; i < 8; i++) {
                fma2(acc[i][0], ap[i], w0);
                fma2(acc[i][1], ap[i], w1);
                fma2(acc[i][2], ap[i], w2);
                fma2(acc[i][3], ap[i], w3);
            }
        }
        __syncthreads();
    }

    #pragma unroll
    for (int i = 0; i < 8; i++) {
        const size_t ro = (size_t)(m0 + ty * 8 + i) * HVc + n0;
        #pragma unroll
        for (int j = 0; j < 4; j++) {
            float lo, hi;
            unpack2(acc[i][j], lo, hi);
            *(float2*)&out[ro + 2 * tx + 32 * j] = make_float2(lo, hi);
        }
    }
}

extern "C" void kernel_launch(void* const* d_in, const int* in_sizes, int n_in,
                              void* d_out, int out_size)
{
    const float* qpos   = (const float*)d_in[0];
    const float* kpos   = (const float*)d_in[1];
    const float* values = (const float*)d_in[2];
    const int*   mask   = (const int*)  d_in[3];
    const float* ls     = (const float*)d_in[4];
    const float* w_out  = (const float*)d_in[5];
    float* out = (float*)d_out;

    const int smem_bytes = SMEM_FLOATS * (int)sizeof(float);
    cudaFuncSetAttribute(attend_kernel,
                         cudaFuncAttributeMaxDynamicSharedMemorySize, smem_bytes);

    compact_kernel<<<Bc, 32>>>(mask);
    gather_kernel<<<Bc * 32, NTHREADS>>>(kpos, values);
    attend_kernel<<<Bc * (Lc / TQ), NTHREADS, smem_bytes>>>(qpos, ls);
    proj_kernel<<<dim3(HVc / PN, (Bc * Lc) / PM), 256>>>(w_out, out);
}

// round 7
// speedup vs baseline: 6.0387x; 1.7006x over previous
#include <cuda_runtime.h>

#define Bc 4
#define Lc 2048
#define Hc 8
#define Vc 64
#define HVc 512
#define NTHREADS 256

typedef unsigned long long ull;

__device__ __forceinline__ void fma2(ull &c, ull a, ull b) {
    asm("fma.rn.f32x2 %0, %1, %2, %0;" : "+l"(c) : "l"(a), "l"(b));
}
__device__ __forceinline__ ull pack2(float lo, float hi) {
    ull r; asm("mov.b64 %0, {%1, %2};" : "=l"(r) : "f"(lo), "f"(hi)); return r;
}
__device__ __forceinline__ void unpack2(ull v, float &lo, float &hi) {
    asm("mov.b64 {%0, %1}, %2;" : "=f"(lo), "=f"(hi) : "l"(v));
}
__device__ __forceinline__ float to_tf32(float x) {
    float r; asm("cvt.rna.tf32.f32 %0, %1;" : "=f"(r) : "f"(x)); return r;
}
// D += A(m16k8,row) * B(k8n8,col), tf32
__device__ __forceinline__ void mma8(float* d, const unsigned* a,
                                     unsigned b0, unsigned b1) {
    asm("mma.sync.aligned.m16n8k8.row.col.f32.tf32.tf32.f32 "
        "{%0,%1,%2,%3}, {%4,%5,%6,%7}, {%8,%9}, {%0,%1,%2,%3};"
        : "+f"(d[0]), "+f"(d[1]), "+f"(d[2]), "+f"(d[3])
        : "r"(a[0]), "r"(a[1]), "r"(a[2]), "r"(a[3]), "r"(b0), "r"(b1));
}

// ---- persistent device scratch ----
__device__ float g_att[Bc * Lc * HVc];          // normalized attended
__device__ float g_vb[Bc * 256 * 64 * 32 * 2];  // V in b-fragment order (tf32)
__device__ float g_kpos_c[Bc * Lc * 3];         // compacted key positions (pad=1000)
__device__ int   g_idx[Bc * Lc];
__device__ int   g_cnt[Bc];

// ================= compaction =================
__global__ void compact_kernel(const int* __restrict__ mask)
{
    const int b = blockIdx.x;
    const int lane = threadIdx.x;
    int cnt = 0;
    for (int k0 = 0; k0 < Lc; k0 += 32) {
        const int k = k0 + lane;
        const bool u = (mask[b * Lc + k] == 0);
        const unsigned bal = __ballot_sync(0xFFFFFFFFu, u);
        if (u) {
            const int pos = cnt + __popc(bal & ((1u << lane) - 1u));
            g_idx[b * Lc + pos] = k;
        }
        cnt += __popc(bal);
    }
    if (lane == 0) g_cnt[b] = cnt;
}

// ====== gather: values -> b-fragment layout (tf32), kpos compacted ======
// word index for V[j][c] (j = compacted key, c = h*64 + n*8 + gr):
//   ksg=j>>3, kk=j&7, tc=kk&3, reg=kk>>2
//   idx = ((((b*256+ksg)*64 + h*8 + n)*32 + gr*4 + tc)*2 + reg
__global__ void gather_kernel(const float* __restrict__ kpos,
                              const float* __restrict__ values)
{
    const int b  = blockIdx.x >> 5;
    const int j0 = (blockIdx.x & 31) * 64;
    const int tid = threadIdx.x;
    __shared__ int s_idx[64];
    __shared__ int s_n[2];

    if (tid == 0) { int c = g_cnt[b]; s_n[0] = c; s_n[1] = (c + 31) & ~31; }
    if (tid < 64 && j0 + tid < Lc) s_idx[tid] = g_idx[b * Lc + j0 + tid];
    __syncthreads();
    const int cnt = s_n[0];
    const int pad = s_n[1];
    const int jend = min(j0 + 64, pad);
    if (jend <= j0) return;
    const int nrows = jend - j0;

    const float4* v4 = (const float4*)values;
    for (int e = tid; e < nrows * 128; e += NTHREADS) {
        const int jl = e >> 7;
        const int c4 = e & 127;             // cols 4*c4 .. 4*c4+3
        const int j  = j0 + jl;
        float4 v;
        if (j < cnt) v = v4[(size_t)(b * Lc + s_idx[jl]) * 128 + c4];
        else         v = make_float4(0.f, 0.f, 0.f, 0.f);
        v.x = to_tf32(v.x); v.y = to_tf32(v.y);
        v.z = to_tf32(v.z); v.w = to_tf32(v.w);
        const int ksg = j >> 3, kk = j & 7;
        const int tc = kk & 3, reg = kk >> 2;
        const float* pv = &v.x;
        #pragma unroll
        for (int t = 0; t < 4; t++) {
            const int c = c4 * 4 + t;
            const int h = c >> 6, n = (c >> 3) & 7, gr = c & 7;
            const size_t idx =
                ((((size_t)b * 256 + ksg) * 64 + h * 8 + n) * 32 + gr * 4 + tc) * 2 + reg;
            g_vb[idx] = pv[t];
        }
    }
    for (int e = tid; e < nrows * 3; e += NTHREADS) {
        const int jl = e / 3;
        const int d  = e % 3;
        const int j  = j0 + jl;
        float p = (j < cnt) ? kpos[(size_t)(b * Lc + s_idx[jl]) * 3 + d] : 1000.0f;
        g_kpos_c[(size_t)(b * Lc + j) * 3 + d] = p;
    }
}

// =========================== attend: tf32 mma.sync ===========================
// block: 32 queries x 8 heads; warp = head; M=32 (2 m16), N=64 (8 n8), K tile 32.
__global__ __launch_bounds__(NTHREADS, 2)
void attend_kernel(const float* __restrict__ qpos,
                   const float* __restrict__ ls)
{
    __shared__ float s_S[8 * 1152];   // [h][q*36 + k]
    __shared__ float s_kx[32], s_ky[32], s_kz[32];
    __shared__ float s_qp[96];
    __shared__ float s_ils[8];

    const int tid  = threadIdx.x;
    const int lane = tid & 31;
    const int warp = tid >> 5;
    const int gr = lane >> 2;
    const int tc = lane & 3;
    const int b  = blockIdx.x >> 6;
    const int qt = blockIdx.x & 63;

    if (tid < 96) s_qp[tid] = qpos[(b * Lc + qt * 32) * 3 + tid];
    if (tid < 8) { float l = ls[tid]; s_ils[tid] = 1.0f / (l * l); }
    __syncthreads();

    // phase-A persona: q = gr + 8*(warp&3), k-half = (warp>>2)
    const int qa = gr + 8 * (warp & 3);
    const int kK = (warp >> 2) * 16;
    const float qx = s_qp[qa * 3 + 0];
    const float qy = s_qp[qa * 3 + 1];
    const float qz = s_qp[qa * 3 + 2];
    float rils[8];
    #pragma unroll
    for (int h = 0; h < 8; h++) rils[h] = s_ils[h];

    const int nk_pad = (g_cnt[b] + 31) & ~31;

    float acc[2][8][4];
    float dacc[2][4];
    #pragma unroll
    for (int m = 0; m < 2; m++) {
        #pragma unroll
        for (int n = 0; n < 8; n++)
            #pragma unroll
            for (int r = 0; r < 4; r++) acc[m][n][r] = 0.0f;
        #pragma unroll
        for (int r = 0; r < 4; r++) dacc[m][r] = 0.0f;
    }

    const unsigned bone = __float_as_uint(1.0f);
    const float2* vb2 = (const float2*)g_vb;

    for (int k0 = 0; k0 < nk_pad; k0 += 32) {
        __syncthreads();                       // previous tile's readers done
        if (tid < 32) {
            const float* kp = g_kpos_c + (size_t)(b * Lc + k0 + tid) * 3;
            s_kx[tid] = kp[0];
            s_ky[tid] = kp[1];
            s_kz[tid] = kp[2];
        }
        __syncthreads();

        // phase A: S[h][q][k] = tf32(exp(-d2/ls^2)); d2 shared across heads
        #pragma unroll
        for (int j = 0; j < 4; j++) {
            const int k = kK + tc + 4 * j;
            const float dx = qx - s_kx[k];
            const float dy = qy - s_ky[k];
            const float dz = qz - s_kz[k];
            const float d2 = dx * dx + dy * dy + dz * dz;
            float* sp = s_S + qa * 36 + k;
            #pragma unroll
            for (int h = 0; h < 8; h++)
                sp[h * 1152] = to_tf32(__expf(-d2 * rils[h]));
        }
        __syncthreads();

        // mma phase: warp = head
        const float* Sh = s_S + warp * 1152;
        const size_t vbase =
            (((size_t)b * 256 + (k0 >> 3)) * 64 + warp * 8) * 32 + lane;
        #pragma unroll
        for (int ks = 0; ks < 4; ks++) {
            const int kc = ks * 8 + tc;
            unsigned a0[4], a1[4];
            a0[0] = __float_as_uint(Sh[(gr)      * 36 + kc]);
            a0[1] = __float_as_uint(Sh[(gr + 8)  * 36 + kc]);
            a0[2] = __float_as_uint(Sh[(gr)      * 36 + kc + 4]);
            a0[3] = __float_as_uint(Sh[(gr + 8)  * 36 + kc + 4]);
            a1[0] = __float_as_uint(Sh[(gr + 16) * 36 + kc]);
            a1[1] = __float_as_uint(Sh[(gr + 24) * 36 + kc]);
            a1[2] = __float_as_uint(Sh[(gr + 16) * 36 + kc + 4]);
            a1[3] = __float_as_uint(Sh[(gr + 24) * 36 + kc + 4]);
            const float2* vp = vb2 + vbase + (size_t)ks * (64 * 32);
            #pragma unroll
            for (int n = 0; n < 8; n++) {
                const float2 bb = vp[n * 32];
                const unsigned b0 = __float_as_uint(bb.x);
                const unsigned b1 = __float_as_uint(bb.y);
                mma8(acc[0][n], a0, b0, b1);
                mma8(acc[1][n], a1, b0, b1);
            }
            mma8(dacc[0], a0, bone, bone);     // den rows, free via ones-column
            mma8(dacc[1], a1, bone, bone);
        }
    }

    // epilogue: each thread holds den for exactly its 4 output rows
    #pragma unroll
    for (int m = 0; m < 2; m++) {
        const float i0 = 1.0f / (dacc[m][0] + 1e-5f);   // row gr
        const float i1 = 1.0f / (dacc[m][2] + 1e-5f);   // row gr+8
        const int q0 = qt * 32 + m * 16 + gr;
        const size_t rb = (size_t)(b * Lc + q0) * HVc + warp * 64 + 2 * tc;
        #pragma unroll
        for (int n = 0; n < 8; n++) {
            *(float2*)&g_att[rb + n * 8] =
                make_float2(acc[m][n][0] * i0, acc[m][n][1] * i0);
            *(float2*)&g_att[rb + 8 * HVc + n * 8] =
                make_float2(acc[m][n][2] * i1, acc[m][n][3] * i1);
        }
    }
}

// ====== projection: out[8192,512] = g_att @ W^T, 128x128 tile, f32x2 ======
#define PM 128
#define PN 128
#define PK 16

__global__ __launch_bounds__(256, 2)
void proj_kernel(const float* __restrict__ W, float* __restrict__ out)
{
    __shared__ __align__(16) float As[PK][PM + 4];
    __shared__ __align__(16) float Ws[PK][PN + 2];

    const int tid = threadIdx.x;
    const int m0 = blockIdx.y * PM;
    const int n0 = blockIdx.x * PN;
    const int tx = tid & 15;
    const int ty = tid >> 4;

    const int lrow = tid >> 1;
    const int lk   = (tid & 1) * 8;

    ull acc[8][4];
    #pragma unroll
    for (int i = 0; i < 8; i++)
        #pragma unroll
        for (int j = 0; j < 4; j++) acc[i][j] = 0ULL;

    float4 ra0 = *(const float4*)&g_att[(size_t)(m0 + lrow) * HVc + lk];
    float4 ra1 = *(const float4*)&g_att[(size_t)(m0 + lrow) * HVc + lk + 4];
    float4 rw0 = *(const float4*)&W[(size_t)(n0 + lrow) * HVc + lk];
    float4 rw1 = *(const float4*)&W[(size_t)(n0 + lrow) * HVc + lk + 4];

    for (int k0 = 0; k0 < HVc; k0 += PK) {
        As[lk + 0][lrow] = ra0.x; As[lk + 1][lrow] = ra0.y;
        As[lk + 2][lrow] = ra0.z; As[lk + 3][lrow] = ra0.w;
        As[lk + 4][lrow] = ra1.x; As[lk + 5][lrow] = ra1.y;
        As[lk + 6][lrow] = ra1.z; As[lk + 7][lrow] = ra1.w;
        Ws[lk + 0][lrow] = rw0.x; Ws[lk + 1][lrow] = rw0.y;
        Ws[lk + 2][lrow] = rw0.z; Ws[lk + 3][lrow] = rw0.w;
        Ws[lk + 4][lrow] = rw1.x; Ws[lk + 5][lrow] = rw1.y;
        Ws[lk + 6][lrow] = rw1.z; Ws[lk + 7][lrow] = rw1.w;
        __syncthreads();

        if (k0 + PK < HVc) {
            const int kn = k0 + PK;
            ra0 = *(const float4*)&g_att[(size_t)(m0 + lrow) * HVc + kn + lk];
            ra1 = *(const float4*)&g_att[(size_t)(m0 + lrow) * HVc + kn + lk + 4];
            rw0 = *(const float4*)&W[(size_t)(n0 + lrow) * HVc + kn + lk];
            rw1 = *(const float4*)&W[(size_t)(n0 + lrow) * HVc + kn + lk + 4];
        }

        #pragma unroll
        for (int k = 0; k < PK; k++) {
            float4 a0 = *(const float4*)&As[k][ty * 8];
            float4 a1 = *(const float4*)&As[k][ty * 8 + 4];
            ull ap[8];
            ap[0] = pack2(a0.x, a0.x); ap[1] = pack2(a0.y, a0.y);
            ap[2] = pack2(a0.z, a0.z); ap[3] = pack2(a0.w, a0.w);
            ap[4] = pack2(a1.x, a1.x); ap[5] = pack2(a1.y, a1.y);
            ap[6] = pack2(a1.z, a1.z); ap[7] = pack2(a1.w, a1.w);
            const ull w0 = *(const ull*)&Ws[k][2 * tx];
            const ull w1 = *(const ull*)&Ws[k][2 * tx + 32];
            const ull w2 = *(const ull*)&Ws[k][2 * tx + 64];
            const ull w3 = *(const ull*)&Ws[k][2 * tx + 96];
            #pragma unroll
            for (int i = 0; i < 8; i++) {
                fma2(acc[i][0], ap[i], w0);
                fma2(acc[i][1], ap[i], w1);
                fma2(acc[i][2], ap[i], w2);
                fma2(acc[i][3], ap[i], w3);
            }
        }
        __syncthreads();
    }

    #pragma unroll
    for (int i = 0; i < 8; i++) {
        const size_t ro = (size_t)(m0 + ty * 8 + i) * HVc + n0;
        #pragma unroll
        for (int j = 0; j < 4; j++) {
            float lo, hi;
            unpack2(acc[i][j], lo, hi);
            *(float2*)&out[ro + 2 * tx + 32 * j] = make_float2(lo, hi);
        }
    }
}

extern "C" void kernel_launch(void* const* d_in, const int* in_sizes, int n_in,
                              void* d_out, int out_size)
{
    const float* qpos   = (const float*)d_in[0];
    const float* kpos   = (const float*)d_in[1];
    const float* values = (const float*)d_in[2];
    const int*   mask   = (const int*)  d_in[3];
    const float* ls     = (const float*)d_in[4];
    const float* w_out  = (const float*)d_in[5];
    float* out = (float*)d_out;

    compact_kernel<<<Bc, 32>>>(mask);
    gather_kernel<<<Bc * 32, NTHREADS>>>(kpos, values);
    attend_kernel<<<Bc * (Lc / 32), NTHREADS>>>(qpos, ls);
    proj_kernel<<<dim3(HVc / PN, (Bc * Lc) / PM), 256>>>(w_out, out);
}